// round 3
// baseline (speedup 1.0000x reference)
#include <cuda_runtime.h>

#define IN_SIZE 448
#define OUT_SIZE 224
#define BATCH 64
#define NTHREADS 224
#define SM_W 456   // staged row width (floats), >= 451 worst case

// Separable tables
__device__ float4 g_rowtab[BATCH * OUT_SIZE];  // {r0i*448, r1i*448, a0, a1} (ints as float bits)
__device__ float4 g_coltab[BATCH * OUT_SIZE];  // {c0i, c1i, b0, b1}
__device__ int2   g_batchinfo[BATCH];          // {c_lo4 (16B-aligned col start), n4 (float4 count)}

__device__ __forceinline__ float sig10(float z) {
    return 1.0f / (1.0f + expf(-10.0f * z));
}

// ---------------------------------------------------------------------------
// Kernel A: precompute separable tables. grid=64, block=224.
// ---------------------------------------------------------------------------
__global__ void __launch_bounds__(NTHREADS) precompute_tables(
    const float* __restrict__ locs)
{
    const int b = blockIdx.x;
    const int j = threadIdx.x;

    float tx = locs[b * 3 + 0];
    float ty = locs[b * 3 + 1];
    float tl = locs[b * 3 + 2];

    tl = fmaxf(tl, 448.0f / 3.0f);
    tx = fminf(fmaxf(tx, tl), (float)IN_SIZE - tl);
    ty = fminf(fmaxf(ty, tl), (float)IN_SIZE - tl);

    const float w_off = fmaxf(floorf(tx - tl), 0.0f);
    const float h_off = fmaxf(floorf(ty - tl), 0.0f);
    const float w_end = fminf(floorf(tx + tl), (float)IN_SIZE);
    const float h_end = fminf(floorf(ty + tl), (float)IN_SIZE);

    const float jf = (float)j;

    // row entry
    {
        const float src_r = w_off + (jf * (w_end - w_off - 1.0f)) / (float)(OUT_SIZE - 1);
        float r0 = fminf(fmaxf(floorf(src_r), 0.0f), (float)(IN_SIZE - 1));
        const float wr = src_r - r0;
        const int r0i = (int)r0;
        const int r1i = min(r0i + 1, IN_SIZE - 1);
        const float mrow0 = sig10((float)r0i - w_off) - sig10((float)r0i - w_end);
        const float mrow1 = sig10((float)r1i - w_off) - sig10((float)r1i - w_end);
        float4 e;
        e.x = __int_as_float(r0i * IN_SIZE);
        e.y = __int_as_float(r1i * IN_SIZE);
        e.z = (1.0f - wr) * mrow0;
        e.w = wr * mrow1;
        g_rowtab[b * OUT_SIZE + j] = e;
    }

    // col entry
    {
        const float src_c = h_off + (jf * (h_end - h_off - 1.0f)) / (float)(OUT_SIZE - 1);
        float c0 = fminf(fmaxf(floorf(src_c), 0.0f), (float)(IN_SIZE - 1));
        const float wc = src_c - c0;
        const int c0i = (int)c0;
        const int c1i = min(c0i + 1, IN_SIZE - 1);
        const float mcol0 = sig10((float)c0i - h_off) - sig10((float)c0i - h_end);
        const float mcol1 = sig10((float)c1i - h_off) - sig10((float)c1i - h_end);
        float4 e;
        e.x = __int_as_float(c0i);
        e.y = __int_as_float(c1i);
        e.z = (1.0f - wc) * mcol0;
        e.w = wc * mcol1;
        g_coltab[b * OUT_SIZE + j] = e;
    }

    // per-batch staging window (h_off/h_end are integer-valued floats)
    if (j == 0) {
        const int c_lo = (int)h_off;                       // min c0i
        const int c_hi = min((int)h_end, IN_SIZE - 1);     // max c1i
        const int c_lo4 = c_lo & ~3;                       // float4 alignment
        const int n4 = (c_hi - c_lo4 + 4) >> 2;            // float4 count covering c_hi
        g_batchinfo[b] = make_int2(c_lo4, n4);
    }
}

// ---------------------------------------------------------------------------
// Kernel B: stage 2 input rows x 3 channels in SMEM, then bilinear from SMEM.
// grid=(224 rows, 64 batch), block=224.
// ---------------------------------------------------------------------------
__global__ void __launch_bounds__(NTHREADS) racnn_gather(
    const float* __restrict__ images,
    float* __restrict__ out)
{
    __shared__ float sm[6][SM_W];   // [row(2) * ch(3)][col]

    const int jr = blockIdx.x;
    const int b  = blockIdx.y;
    const int jc = threadIdx.x;

    const int2 bi = g_batchinfo[b];
    const int c_lo4 = bi.x;
    const int n4    = bi.y;

    const float4 re = g_rowtab[b * OUT_SIZE + jr];   // warp-uniform
    const int   r0off = __float_as_int(re.x);
    const int   r1off = __float_as_int(re.y);
    const float a0 = re.z;
    const float a1 = re.w;

    const int img_base = b * 3 * IN_SIZE * IN_SIZE + c_lo4;

    // ---- stage: 6 row-channel segments, coalesced float4 loads ----
#pragma unroll
    for (int rc = 0; rc < 6; rc++) {
        const int ch  = rc >> 1;                 // 0,0,1,1,2,2
        const int rof = (rc & 1) ? r1off : r0off;
        const float4* src = (const float4*)(images + img_base + ch * (IN_SIZE * IN_SIZE) + rof);
        float4* dst = (float4*)sm[rc];
        for (int c4 = jc; c4 < n4; c4 += NTHREADS)
            dst[c4] = __ldg(src + c4);
    }
    __syncthreads();

    // ---- compute ----
    const float4 ce = g_coltab[b * OUT_SIZE + jc];
    const int   s0 = __float_as_int(ce.x) - c_lo4;
    const int   s1 = __float_as_int(ce.y) - c_lo4;
    const float b0 = ce.z;
    const float b1 = ce.w;

    const int out_base = b * 3 * OUT_SIZE * OUT_SIZE + jr * OUT_SIZE + jc;

#pragma unroll
    for (int ch = 0; ch < 3; ch++) {
        const float x00 = sm[ch * 2 + 0][s0];
        const float x01 = sm[ch * 2 + 0][s1];
        const float x10 = sm[ch * 2 + 1][s0];
        const float x11 = sm[ch * 2 + 1][s1];

        const float top = fmaf(b1, x01, b0 * x00);
        const float bot = fmaf(b1, x11, b0 * x10);
        out[out_base + ch * (OUT_SIZE * OUT_SIZE)] = fmaf(a1, bot, a0 * top);
    }
}

extern "C" void kernel_launch(void* const* d_in, const int* in_sizes, int n_in,
                              void* d_out, int out_size) {
    const float* images = (const float*)d_in[0];
    const float* locs   = (const float*)d_in[1];
    float* out = (float*)d_out;

    precompute_tables<<<BATCH, NTHREADS>>>(locs);

    dim3 grid(OUT_SIZE, BATCH);
    racnn_gather<<<grid, NTHREADS>>>(images, out);
}

// round 4
// speedup vs baseline: 2.8553x; 2.8553x over previous
#include <cuda_runtime.h>

#define IN_SIZE 448
#define OUT_SIZE 224
#define BATCH 64
#define NTHREADS 224
#define ROWS_PER_BLK 4

// Separable tables: {index0, index1, weight0, weight1} per (batch, j)
__device__ float4 g_rowtab[BATCH * OUT_SIZE];  // {r0i*448, r1i*448, a0, a1} (int bits in .x/.y)
__device__ float4 g_coltab[BATCH * OUT_SIZE];  // {c0i, c1i, b0, b1}

__device__ __forceinline__ float sig10(float z) {
    return 1.0f / (1.0f + expf(-10.0f * z));
}

// ---------------------------------------------------------------------------
// Kernel A: precompute separable crop/resize tables. grid=64, block=224.
// ---------------------------------------------------------------------------
__global__ void __launch_bounds__(NTHREADS) precompute_tables(
    const float* __restrict__ locs)
{
    const int b = blockIdx.x;
    const int j = threadIdx.x;

    float tx = locs[b * 3 + 0];
    float ty = locs[b * 3 + 1];
    float tl = locs[b * 3 + 2];

    tl = fmaxf(tl, 448.0f / 3.0f);
    tx = fminf(fmaxf(tx, tl), (float)IN_SIZE - tl);
    ty = fminf(fmaxf(ty, tl), (float)IN_SIZE - tl);

    const float w_off = fmaxf(floorf(tx - tl), 0.0f);
    const float h_off = fmaxf(floorf(ty - tl), 0.0f);
    const float w_end = fminf(floorf(tx + tl), (float)IN_SIZE);
    const float h_end = fminf(floorf(ty + tl), (float)IN_SIZE);

    const float jf = (float)j;

    // row entry
    {
        const float src_r = w_off + (jf * (w_end - w_off - 1.0f)) / (float)(OUT_SIZE - 1);
        float r0 = fminf(fmaxf(floorf(src_r), 0.0f), (float)(IN_SIZE - 1));
        const float wr = src_r - r0;
        const int r0i = (int)r0;
        const int r1i = min(r0i + 1, IN_SIZE - 1);
        const float mrow0 = sig10((float)r0i - w_off) - sig10((float)r0i - w_end);
        const float mrow1 = sig10((float)r1i - w_off) - sig10((float)r1i - w_end);
        float4 e;
        e.x = __int_as_float(r0i * IN_SIZE);
        e.y = __int_as_float(r1i * IN_SIZE);
        e.z = (1.0f - wr) * mrow0;
        e.w = wr * mrow1;
        g_rowtab[b * OUT_SIZE + j] = e;
    }

    // col entry
    {
        const float src_c = h_off + (jf * (h_end - h_off - 1.0f)) / (float)(OUT_SIZE - 1);
        float c0 = fminf(fmaxf(floorf(src_c), 0.0f), (float)(IN_SIZE - 1));
        const float wc = src_c - c0;
        const int c0i = (int)c0;
        const int c1i = min(c0i + 1, IN_SIZE - 1);
        const float mcol0 = sig10((float)c0i - h_off) - sig10((float)c0i - h_end);
        const float mcol1 = sig10((float)c1i - h_off) - sig10((float)c1i - h_end);
        float4 e;
        e.x = __int_as_float(c0i);
        e.y = __int_as_float(c1i);
        e.z = (1.0f - wc) * mcol0;
        e.w = wc * mcol1;
        g_coltab[b * OUT_SIZE + j] = e;
    }
}

// ---------------------------------------------------------------------------
// Kernel B: gather + weighted sum. grid=(56, 64), block=224.
// Each block handles ROWS_PER_BLK output rows of one batch image.
// No launch_bounds: let ptxas front-batch the scattered loads.
// ---------------------------------------------------------------------------
__global__ void racnn_gather(
    const float* __restrict__ images,
    float* __restrict__ out)
{
    const int jr0 = blockIdx.x * ROWS_PER_BLK;
    const int b   = blockIdx.y;
    const int jc  = threadIdx.x;

    // col entry: coalesced 16B load, reused for all rows
    const float4 ce = g_coltab[b * OUT_SIZE + jc];
    const int   c0i = __float_as_int(ce.x);
    const int   c1i = __float_as_int(ce.y);
    const float b0  = ce.z;
    const float b1  = ce.w;

    const int img_base = b * 3 * IN_SIZE * IN_SIZE;
    const int out_base = b * 3 * OUT_SIZE * OUT_SIZE + jr0 * OUT_SIZE + jc;

    // hoist all row entries (warp-uniform broadcasts)
    int   r0off[ROWS_PER_BLK], r1off[ROWS_PER_BLK];
    float a0[ROWS_PER_BLK], a1[ROWS_PER_BLK];
#pragma unroll
    for (int r = 0; r < ROWS_PER_BLK; r++) {
        const float4 re = g_rowtab[b * OUT_SIZE + jr0 + r];
        r0off[r] = __float_as_int(re.x);
        r1off[r] = __float_as_int(re.y);
        a0[r] = re.z;
        a1[r] = re.w;
    }

    // gather all taps: 4 rows x 3 ch x 4 taps = 48 loads, batched for MLP
#pragma unroll
    for (int r = 0; r < ROWS_PER_BLK; r++) {
        const int p0 = img_base + r0off[r];
        const int p1 = img_base + r1off[r];
        float x00[3], x01[3], x10[3], x11[3];
#pragma unroll
        for (int ch = 0; ch < 3; ch++) {
            const int cofs = ch * (IN_SIZE * IN_SIZE);
            x00[ch] = __ldg(images + p0 + cofs + c0i);
            x01[ch] = __ldg(images + p0 + cofs + c1i);
            x10[ch] = __ldg(images + p1 + cofs + c0i);
            x11[ch] = __ldg(images + p1 + cofs + c1i);
        }
#pragma unroll
        for (int ch = 0; ch < 3; ch++) {
            const float top = fmaf(b1, x01[ch], b0 * x00[ch]);
            const float bot = fmaf(b1, x11[ch], b0 * x10[ch]);
            out[out_base + ch * (OUT_SIZE * OUT_SIZE) + r * OUT_SIZE] =
                fmaf(a1[r], bot, a0[r] * top);
        }
    }
}

extern "C" void kernel_launch(void* const* d_in, const int* in_sizes, int n_in,
                              void* d_out, int out_size) {
    const float* images = (const float*)d_in[0];
    const float* locs   = (const float*)d_in[1];
    float* out = (float*)d_out;

    precompute_tables<<<BATCH, NTHREADS>>>(locs);

    dim3 grid(OUT_SIZE / ROWS_PER_BLK, BATCH);
    racnn_gather<<<grid, NTHREADS>>>(images, out);
}

// round 5
// speedup vs baseline: 2.9487x; 1.0327x over previous
#include <cuda_runtime.h>

#define IN_SIZE 448
#define OUT_SIZE 224
#define BATCH 64
#define NTHREADS 224
#define ROWS_PER_BLK 4

// fast sigmoid(10z): __expf is a single MUFU.EX2-based intrinsic.
// Saturates correctly: __expf(+big)=inf -> 0, __expf(-big)=0 -> 1.
__device__ __forceinline__ float sig10f(float z) {
    return 1.0f / (1.0f + __expf(-10.0f * z));
}

// ---------------------------------------------------------------------------
// Single fused kernel. grid=(56, 64), block=224.
// Each block: 4 output rows of one batch image.
//  - threads 0..3 compute the 4 row entries (indices + row weights) -> smem
//  - every thread computes its own col entry inline
//  - then 48 gather taps + 12 stores, exactly as the R4 gather.
// Index math (floor, true division) is exact fp32, matching the reference;
// only the smooth sigmoid masks use __expf.
// ---------------------------------------------------------------------------
__global__ void __launch_bounds__(NTHREADS) racnn_fused(
    const float* __restrict__ images,
    const float* __restrict__ locs,
    float* __restrict__ out)
{
    __shared__ float4 s_rowe[ROWS_PER_BLK];   // {r0off(int bits), r1off(int bits), a0, a1}

    const int jr0 = blockIdx.x * ROWS_PER_BLK;
    const int b   = blockIdx.y;
    const int jc  = threadIdx.x;

    // ---- per-batch crop params (broadcast loads, ~20 flops) ----
    float tx = locs[b * 3 + 0];
    float ty = locs[b * 3 + 1];
    float tl = locs[b * 3 + 2];

    tl = fmaxf(tl, 448.0f / 3.0f);
    tx = fminf(fmaxf(tx, tl), (float)IN_SIZE - tl);
    ty = fminf(fmaxf(ty, tl), (float)IN_SIZE - tl);

    const float w_off = fmaxf(floorf(tx - tl), 0.0f);
    const float h_off = fmaxf(floorf(ty - tl), 0.0f);
    const float w_end = fminf(floorf(tx + tl), (float)IN_SIZE);
    const float h_end = fminf(floorf(ty + tl), (float)IN_SIZE);

    // ---- row entries: threads 0..3, one row each ----
    if (jc < ROWS_PER_BLK) {
        const float jf = (float)(jr0 + jc);
        const float src_r = w_off + (jf * (w_end - w_off - 1.0f)) / (float)(OUT_SIZE - 1);
        float r0 = fminf(fmaxf(floorf(src_r), 0.0f), (float)(IN_SIZE - 1));
        const float wr = src_r - r0;
        const int r0i = (int)r0;
        const int r1i = min(r0i + 1, IN_SIZE - 1);
        const float mrow0 = sig10f((float)r0i - w_off) - sig10f((float)r0i - w_end);
        const float mrow1 = sig10f((float)r1i - w_off) - sig10f((float)r1i - w_end);
        float4 e;
        e.x = __int_as_float(r0i * IN_SIZE);
        e.y = __int_as_float(r1i * IN_SIZE);
        e.z = (1.0f - wr) * mrow0;
        e.w = wr * mrow1;
        s_rowe[jc] = e;
    }

    // ---- col entry: every thread, its own column ----
    const float jf = (float)jc;
    const float src_c = h_off + (jf * (h_end - h_off - 1.0f)) / (float)(OUT_SIZE - 1);
    float c0 = fminf(fmaxf(floorf(src_c), 0.0f), (float)(IN_SIZE - 1));
    const float wc = src_c - c0;
    const int c0i = (int)c0;
    const int c1i = min(c0i + 1, IN_SIZE - 1);
    const float mcol0 = sig10f((float)c0i - h_off) - sig10f((float)c0i - h_end);
    const float mcol1 = sig10f((float)c1i - h_off) - sig10f((float)c1i - h_end);
    const float b0 = (1.0f - wc) * mcol0;
    const float b1 = wc * mcol1;

    __syncthreads();

    const int img_base = b * 3 * IN_SIZE * IN_SIZE;
    const int out_base = b * 3 * OUT_SIZE * OUT_SIZE + jr0 * OUT_SIZE + jc;

#pragma unroll
    for (int r = 0; r < ROWS_PER_BLK; r++) {
        const float4 re = s_rowe[r];           // smem broadcast
        const int   p0 = img_base + __float_as_int(re.x);
        const int   p1 = img_base + __float_as_int(re.y);
        const float a0 = re.z;
        const float a1 = re.w;

        float x00[3], x01[3], x10[3], x11[3];
#pragma unroll
        for (int ch = 0; ch < 3; ch++) {
            const int cofs = ch * (IN_SIZE * IN_SIZE);
            x00[ch] = __ldg(images + p0 + cofs + c0i);
            x01[ch] = __ldg(images + p0 + cofs + c1i);
            x10[ch] = __ldg(images + p1 + cofs + c0i);
            x11[ch] = __ldg(images + p1 + cofs + c1i);
        }
#pragma unroll
        for (int ch = 0; ch < 3; ch++) {
            const float top = fmaf(b1, x01[ch], b0 * x00[ch]);
            const float bot = fmaf(b1, x11[ch], b0 * x10[ch]);
            out[out_base + ch * (OUT_SIZE * OUT_SIZE) + r * OUT_SIZE] =
                fmaf(a1, bot, a0 * top);
        }
    }
}

extern "C" void kernel_launch(void* const* d_in, const int* in_sizes, int n_in,
                              void* d_out, int out_size) {
    const float* images = (const float*)d_in[0];
    const float* locs   = (const float*)d_in[1];
    float* out = (float*)d_out;

    dim3 grid(OUT_SIZE / ROWS_PER_BLK, BATCH);
    racnn_fused<<<grid, NTHREADS>>>(images, locs, out);
}

// round 6
// speedup vs baseline: 3.1887x; 1.0814x over previous
#include <cuda_runtime.h>

#define IN_SIZE 448
#define OUT_SIZE 224
#define BATCH 64
#define NTHREADS 224
#define ROWS_PER_BLK 8

// fast sigmoid(10z): EX2+RCP MUFU ops. Saturates correctly at both ends.
__device__ __forceinline__ float sig10f(float z) {
    return 1.0f / (1.0f + __expf(-10.0f * z));
}

// ---------------------------------------------------------------------------
// Fused kernel. grid=(28, 64), block=224. Each block: 8 output rows.
//  - threads 0..7 compute the 8 row entries -> smem
//  - every thread computes its own col entry inline
//  - gather: 8 rows x 3ch x 4 taps, batched 2 rows (24 loads) at a time.
// launch_bounds(224,4): reg budget ~72 so ptxas can keep ~24 LDGs in flight.
// ---------------------------------------------------------------------------
__global__ void __launch_bounds__(NTHREADS, 4) racnn_fused(
    const float* __restrict__ images,
    const float* __restrict__ locs,
    float* __restrict__ out)
{
    __shared__ float4 s_rowe[ROWS_PER_BLK];   // {r0off(int bits), r1off(int bits), a0, a1}

    const int jr0 = blockIdx.x * ROWS_PER_BLK;
    const int b   = blockIdx.y;
    const int jc  = threadIdx.x;

    // ---- per-batch crop params ----
    float tx = locs[b * 3 + 0];
    float ty = locs[b * 3 + 1];
    float tl = locs[b * 3 + 2];

    tl = fmaxf(tl, 448.0f / 3.0f);
    tx = fminf(fmaxf(tx, tl), (float)IN_SIZE - tl);
    ty = fminf(fmaxf(ty, tl), (float)IN_SIZE - tl);

    const float w_off = fmaxf(floorf(tx - tl), 0.0f);
    const float h_off = fmaxf(floorf(ty - tl), 0.0f);
    const float w_end = fminf(floorf(tx + tl), (float)IN_SIZE);
    const float h_end = fminf(floorf(ty + tl), (float)IN_SIZE);

    // ---- row entries: threads 0..7 ----
    if (jc < ROWS_PER_BLK) {
        const float jf = (float)(jr0 + jc);
        const float src_r = w_off + (jf * (w_end - w_off - 1.0f)) / (float)(OUT_SIZE - 1);
        float r0 = fminf(fmaxf(floorf(src_r), 0.0f), (float)(IN_SIZE - 1));
        const float wr = src_r - r0;
        const int r0i = (int)r0;
        const int r1i = min(r0i + 1, IN_SIZE - 1);
        const float mrow0 = sig10f((float)r0i - w_off) - sig10f((float)r0i - w_end);
        const float mrow1 = sig10f((float)r1i - w_off) - sig10f((float)r1i - w_end);
        float4 e;
        e.x = __int_as_float(r0i * IN_SIZE);
        e.y = __int_as_float(r1i * IN_SIZE);
        e.z = (1.0f - wr) * mrow0;
        e.w = wr * mrow1;
        s_rowe[jc] = e;
    }

    // ---- col entry: per thread ----
    const float jf = (float)jc;
    const float src_c = h_off + (jf * (h_end - h_off - 1.0f)) / (float)(OUT_SIZE - 1);
    float c0 = fminf(fmaxf(floorf(src_c), 0.0f), (float)(IN_SIZE - 1));
    const float wc = src_c - c0;
    const int c0i = (int)c0;
    const int c1i = min(c0i + 1, IN_SIZE - 1);
    const float mcol0 = sig10f((float)c0i - h_off) - sig10f((float)c0i - h_end);
    const float mcol1 = sig10f((float)c1i - h_off) - sig10f((float)c1i - h_end);
    const float b0 = (1.0f - wc) * mcol0;
    const float b1 = wc * mcol1;

    __syncthreads();

    const int img_base = b * 3 * IN_SIZE * IN_SIZE;
    const int out_base = b * 3 * OUT_SIZE * OUT_SIZE + jr0 * OUT_SIZE + jc;

    // ---- gather, 2 rows per batch (24 outstanding loads) ----
#pragma unroll
    for (int rp = 0; rp < ROWS_PER_BLK; rp += 2) {
        float x00[2][3], x01[2][3], x10[2][3], x11[2][3];
        float a0[2], a1[2];

#pragma unroll
        for (int u = 0; u < 2; u++) {
            const float4 re = s_rowe[rp + u];
            const int p0 = img_base + __float_as_int(re.x);
            const int p1 = img_base + __float_as_int(re.y);
            a0[u] = re.z;
            a1[u] = re.w;
#pragma unroll
            for (int ch = 0; ch < 3; ch++) {
                const int cofs = ch * (IN_SIZE * IN_SIZE);
                x00[u][ch] = __ldg(images + p0 + cofs + c0i);
                x01[u][ch] = __ldg(images + p0 + cofs + c1i);
                x10[u][ch] = __ldg(images + p1 + cofs + c0i);
                x11[u][ch] = __ldg(images + p1 + cofs + c1i);
            }
        }

#pragma unroll
        for (int u = 0; u < 2; u++) {
#pragma unroll
            for (int ch = 0; ch < 3; ch++) {
                const float top = fmaf(b1, x01[u][ch], b0 * x00[u][ch]);
                const float bot = fmaf(b1, x11[u][ch], b0 * x10[u][ch]);
                const float v = fmaf(a1[u], bot, a0[u] * top);
                __stcs(out + out_base + ch * (OUT_SIZE * OUT_SIZE) + (rp + u) * OUT_SIZE, v);
            }
        }
    }
}

extern "C" void kernel_launch(void* const* d_in, const int* in_sizes, int n_in,
                              void* d_out, int out_size) {
    const float* images = (const float*)d_in[0];
    const float* locs   = (const float*)d_in[1];
    float* out = (float*)d_out;

    dim3 grid(OUT_SIZE / ROWS_PER_BLK, BATCH);
    racnn_fused<<<grid, NTHREADS>>>(images, locs, out);
}

// round 7
// speedup vs baseline: 3.1924x; 1.0012x over previous
#include <cuda_runtime.h>

#define IN_SIZE 448
#define OUT_SIZE 224
#define BATCH 64
#define NTHREADS 224
#define ROWS_PER_BLK 8

// fast sigmoid(10z): MUFU-based; saturates correctly at both ends.
__device__ __forceinline__ float sig10f(float z) {
    return 1.0f / (1.0f + __expf(-10.0f * z));
}

// ---------------------------------------------------------------------------
// Fused kernel. grid=(28, 64), block=224. Each block: 8 output rows.
// Plain launch_bounds -> ptxas targets high occupancy (regs ~32, occ ~80%),
// which R4-R6 showed beats deep per-thread load batching at low occupancy.
// ---------------------------------------------------------------------------
__global__ void __launch_bounds__(NTHREADS) racnn_fused(
    const float* __restrict__ images,
    const float* __restrict__ locs,
    float* __restrict__ out)
{
    __shared__ float4 s_rowe[ROWS_PER_BLK];  // {r0off(int bits), r1off(int bits), a0, a1}

    const int jr0 = blockIdx.x * ROWS_PER_BLK;
    const int b   = blockIdx.y;
    const int jc  = threadIdx.x;

    // ---- per-batch crop params (broadcast) ----
    float tx = locs[b * 3 + 0];
    float ty = locs[b * 3 + 1];
    float tl = locs[b * 3 + 2];

    tl = fmaxf(tl, 448.0f / 3.0f);
    tx = fminf(fmaxf(tx, tl), (float)IN_SIZE - tl);
    ty = fminf(fmaxf(ty, tl), (float)IN_SIZE - tl);

    const float w_off = fmaxf(floorf(tx - tl), 0.0f);
    const float h_off = fmaxf(floorf(ty - tl), 0.0f);
    const float w_end = fminf(floorf(tx + tl), (float)IN_SIZE);
    const float h_end = fminf(floorf(ty + tl), (float)IN_SIZE);

    // ---- row entries: threads 0..7 ----
    if (jc < ROWS_PER_BLK) {
        const float jf = (float)(jr0 + jc);
        const float src_r = w_off + (jf * (w_end - w_off - 1.0f)) / (float)(OUT_SIZE - 1);
        float r0 = fminf(fmaxf(floorf(src_r), 0.0f), (float)(IN_SIZE - 1));
        const float wr = src_r - r0;
        const int r0i = (int)r0;
        const int r1i = min(r0i + 1, IN_SIZE - 1);
        const float mrow0 = sig10f((float)r0i - w_off) - sig10f((float)r0i - w_end);
        const float mrow1 = sig10f((float)r1i - w_off) - sig10f((float)r1i - w_end);
        float4 e;
        e.x = __int_as_float(r0i * IN_SIZE);
        e.y = __int_as_float(r1i * IN_SIZE);
        e.z = (1.0f - wr) * mrow0;
        e.w = wr * mrow1;
        s_rowe[jc] = e;
    }

    // ---- col entry: per thread ----
    const float jf = (float)jc;
    const float src_c = h_off + (jf * (h_end - h_off - 1.0f)) / (float)(OUT_SIZE - 1);
    float c0 = fminf(fmaxf(floorf(src_c), 0.0f), (float)(IN_SIZE - 1));
    const float wc = src_c - c0;
    const int c0i = (int)c0;
    const int c1i = min(c0i + 1, IN_SIZE - 1);
    const float mcol0 = sig10f((float)c0i - h_off) - sig10f((float)c0i - h_end);
    const float mcol1 = sig10f((float)c1i - h_off) - sig10f((float)c1i - h_end);
    const float b0 = (1.0f - wc) * mcol0;
    const float b1 = wc * mcol1;

    __syncthreads();

    const int img_base = b * 3 * IN_SIZE * IN_SIZE;
    const int out_base = b * 3 * OUT_SIZE * OUT_SIZE + jr0 * OUT_SIZE + jc;

    // ---- gather: one row per iteration, 12-load batches (R4's best shape) ----
#pragma unroll
    for (int r = 0; r < ROWS_PER_BLK; r++) {
        const float4 re = s_rowe[r];
        const int   p0 = img_base + __float_as_int(re.x);
        const int   p1 = img_base + __float_as_int(re.y);
        const float a0 = re.z;
        const float a1 = re.w;

        float x00[3], x01[3], x10[3], x11[3];
#pragma unroll
        for (int ch = 0; ch < 3; ch++) {
            const int cofs = ch * (IN_SIZE * IN_SIZE);
            x00[ch] = __ldg(images + p0 + cofs + c0i);
            x01[ch] = __ldg(images + p0 + cofs + c1i);
            x10[ch] = __ldg(images + p1 + cofs + c0i);
            x11[ch] = __ldg(images + p1 + cofs + c1i);
        }
#pragma unroll
        for (int ch = 0; ch < 3; ch++) {
            const float top = fmaf(b1, x01[ch], b0 * x00[ch]);
            const float bot = fmaf(b1, x11[ch], b0 * x10[ch]);
            const float v = fmaf(a1, bot, a0 * top);
            __stcs(out + out_base + ch * (OUT_SIZE * OUT_SIZE) + r * OUT_SIZE, v);
        }
    }
}

extern "C" void kernel_launch(void* const* d_in, const int* in_sizes, int n_in,
                              void* d_out, int out_size) {
    const float* images = (const float*)d_in[0];
    const float* locs   = (const float*)d_in[1];
    float* out = (float*)d_out;

    dim3 grid(OUT_SIZE / ROWS_PER_BLK, BATCH);
    racnn_fused<<<grid, NTHREADS>>>(images, locs, out);
}